// round 10
// baseline (speedup 1.0000x reference)
#include <cuda_runtime.h>
#include <cuda_bf16.h>
#include <cstdint>

// Shapes (fixed): pointcloud (4,16384,3) f32; keys (4096,3) f32; values (4096,64) f32
// Output f32: feats (65536,64) | ids (65536) | pointcloud (196608) = 4456448 elems

#define BN       65536
#define M_KEYS   4096
#define D_FEAT   64
#define PC_ELEMS 196608

#define FEATS_OFF 0
#define IDS_OFF   4194304
#define PC_OFF    4259840

#define G        16
#define NCELLS   (G * G * G)            // 4096
#define BOX      4.75f
#define CELLW    (2.0f * BOX / G)       // 0.59375
#define INVW     (1.0f / CELLW)
// Reference d2 chain abs rounding error <= ~3e-5 for these magnitudes.
#define MARGIN   1e-3f

typedef unsigned long long ull;

// Device scratch (no allocs allowed in kernel_launch).
__device__ int    g_khist[NCELLS];
__device__ int    g_phist[NCELLS];
__device__ int    g_kstart[NCELLS + 1];
__device__ int    g_kcur[NCELLS];
__device__ int    g_pstart[NCELLS + 1];
__device__ int    g_pcur[NCELLS];
__device__ float4 g_skeys[M_KEYS];        // (x, y, z, ||k||^2), cell-sorted
__device__ int    g_skidx[M_KEYS];        // original key index
__device__ float4 g_spts[BN];             // (x, y, z, bitcast orig point idx)

__device__ __forceinline__ int cell_coord(float x) {
    int c = (int)floorf((x + BOX) * INVW);
    return min(max(c, 0), G - 1);
}

// ---------------------------------------------------------------------------
__global__ void __launch_bounds__(256) zero_kernel() {
    int t = blockIdx.x * blockDim.x + threadIdx.x;
    if (t < NCELLS) { g_khist[t] = 0; g_phist[t] = 0; }
}

// ---------------------------------------------------------------------------
__global__ void __launch_bounds__(256) hist_kernel(
    const float* __restrict__ pc, const float* __restrict__ keys)
{
    int t = blockIdx.x * blockDim.x + threadIdx.x;
    if (t < BN) {
        int cx = cell_coord(pc[3*t+0]);
        int cy = cell_coord(pc[3*t+1]);
        int cz = cell_coord(pc[3*t+2]);
        atomicAdd(&g_phist[(cz * G + cy) * G + cx], 1);
    }
    if (t < M_KEYS) {
        int cx = cell_coord(keys[3*t+0]);
        int cy = cell_coord(keys[3*t+1]);
        int cz = cell_coord(keys[3*t+2]);
        atomicAdd(&g_khist[(cz * G + cy) * G + cx], 1);
    }
}

// ---------------------------------------------------------------------------
__global__ void __launch_bounds__(1024) scan_kernel() {
    const bool isK = (blockIdx.x == 0);
    int* hist  = isK ? g_khist  : g_phist;
    int* start = isK ? g_kstart : g_pstart;
    int* cur   = isK ? g_kcur   : g_pcur;

    int t = threadIdx.x;
    int s = 0;
#pragma unroll
    for (int i = 0; i < 4; ++i) s += hist[t * 4 + i];

    __shared__ int sm[1024];
    sm[t] = s;
    __syncthreads();
    for (int off = 1; off < 1024; off <<= 1) {
        int v = (t >= off) ? sm[t - off] : 0;
        __syncthreads();
        sm[t] += v;
        __syncthreads();
    }
    int run = sm[t] - s;

#pragma unroll
    for (int i = 0; i < 4; ++i) {
        int idx = t * 4 + i;
        start[idx] = run;
        cur[idx]   = run;
        run += hist[idx];
    }
    if (t == 1023) start[NCELLS] = run;
}

// ---------------------------------------------------------------------------
__global__ void __launch_bounds__(256) scatter_kernel(
    const float* __restrict__ pc, const float* __restrict__ keys)
{
    int t = blockIdx.x * blockDim.x + threadIdx.x;
    if (t < BN) {
        float x = pc[3*t+0], y = pc[3*t+1], z = pc[3*t+2];
        int c = (cell_coord(z) * G + cell_coord(y)) * G + cell_coord(x);
        int pos = atomicAdd(&g_pcur[c], 1);
        g_spts[pos] = make_float4(x, y, z, __int_as_float(t));
    }
    if (t < M_KEYS) {
        float kx = keys[3*t+0], ky = keys[3*t+1], kz = keys[3*t+2];
        float q = fmaf(kz, kz, fmaf(ky, ky, kx * kx));   // identical ksq chain
        int c = (cell_coord(kz) * G + cell_coord(ky)) * G + cell_coord(kx);
        int pos = atomicAdd(&g_kcur[c], 1);
        g_skeys[pos] = make_float4(kx, ky, kz, q);
        g_skidx[pos] = t;
    }
}

// ---------------------------------------------------------------------------
__device__ __forceinline__ float axis_dist(float p, int c) {
    float lo = (c == 0)     ? -1e30f : (-BOX + (float)c * CELLW);
    float hi = (c == G - 1) ?  1e30f : (-BOX + (float)(c + 1) * CELLW);
    return fmaxf(0.0f, fmaxf(lo - p, p - hi));
}

// Order-preserving float->u32 (and inverse).
__device__ __forceinline__ unsigned ord(float f) {
    unsigned u = __float_as_uint(f);
    return (u & 0x80000000u) ? ~u : (u | 0x80000000u);
}
__device__ __forceinline__ float unord(unsigned u) {
    return __uint_as_float((u & 0x80000000u) ? (u ^ 0x80000000u) : ~u);
}

// Strided exact scan of one cell: lane q evaluates s0+q, s0+q+4, ...
// Reference chain per key; lexicographic (d2, idx) update.
__device__ __forceinline__ void scan_cell_s4(
    int c, int q, float px, float py, float pz, float psq,
    float& best, int& bidx)
{
    int s0 = g_kstart[c];
    int s1 = g_kstart[c + 1];
    for (int s = s0 + q; s < s1; s += 4) {
        float4 k = g_skeys[s];
        float cross = fmaf(pz, k.z, fmaf(py, k.y, px * k.x));
        float d2 = fmaf(-2.0f, cross, psq) + k.w;
        int j = g_skidx[s];
        if (d2 < best || (d2 == best && j < bidx)) { best = d2; bidx = j; }
    }
}

// Group-of-4 lexicographic min via shfl (width 4). Exact and order-free.
__device__ __forceinline__ void group_min(float& best, int& bidx) {
    ull packed = ((ull)ord(best) << 32) | (unsigned)bidx;
    ull o1 = __shfl_xor_sync(0xFFFFFFFFu, packed, 1, 4);
    packed = min(packed, o1);
    ull o2 = __shfl_xor_sync(0xFFFFFFFFu, packed, 2, 4);
    packed = min(packed, o2);
    best = unord((unsigned)(packed >> 32));
    bidx = (int)(packed & 0xFFFFFFFFu);
}

// ---------------------------------------------------------------------------
// K5 (fused): grid argmin with 4 lanes/point + values gather + ids + pc copy.
// Skip rule: lb2 > best + MARGIN (MARGIN >> d2 rounding error) — every key
// whose exact d2 could attain the min IS evaluated with the reference chain.
// Lexicographic (d2, idx) min across lanes/cells == jnp.argmin first-min.
// ---------------------------------------------------------------------------
__global__ void __launch_bounds__(256) argmin_fused_kernel(
    const float* __restrict__ pc,
    const float* __restrict__ values,
    float* __restrict__ out)
{
    int t = blockIdx.x * blockDim.x + threadIdx.x;   // BN*4 threads exactly

    // Fold pointcloud copy (49152 float4s) into the first threads.
    if (t < PC_ELEMS / 4) {
        reinterpret_cast<float4*>(out + PC_OFF)[t] =
            reinterpret_cast<const float4*>(pc)[t];
    }

    int ps = t >> 2;        // sorted point index
    int q  = t & 3;         // lane within point group

    float4 p4 = g_spts[ps];
    float px = p4.x, py = p4.y, pz = p4.z;
    int orig = __float_as_int(p4.w);
    float psq = fmaf(pz, pz, fmaf(py, py, px * px));

    int cx = cell_coord(px);
    int cy = cell_coord(py);
    int cz = cell_coord(pz);

    float best = __int_as_float(0x7f800000);  // +inf
    int   bidx = 0;

    // Pass 1: own cell (strided across 4 lanes), then share.
    scan_cell_s4((cz * G + cy) * G + cx, q, px, py, pz, psq, best, bidx);
    group_min(best, bidx);

    // Pass 2: 26 neighbors with lb pruning.
#pragma unroll
    for (int dz = -1; dz <= 1; ++dz) {
        int cz2 = cz + dz;
        if (cz2 < 0 || cz2 >= G) continue;
        float azd = axis_dist(pz, cz2);
#pragma unroll
        for (int dy = -1; dy <= 1; ++dy) {
            int cy2 = cy + dy;
            if (cy2 < 0 || cy2 >= G) continue;
            float ay = axis_dist(py, cy2);
#pragma unroll
            for (int dx = -1; dx <= 1; ++dx) {
                if (dx == 0 && dy == 0 && dz == 0) continue;
                int cx2 = cx + dx;
                if (cx2 < 0 || cx2 >= G) continue;
                float ax = axis_dist(px, cx2);
                float lb2 = fmaf(ax, ax, fmaf(ay, ay, azd * azd));
                if (lb2 > best + MARGIN) continue;
                scan_cell_s4((cz2 * G + cy2) * G + cx2, q, px, py, pz, psq, best, bidx);
            }
        }
    }
    group_min(best, bidx);

    // Pass 3: rare expanding shells (tail points).
    for (int r = 2; r < G; ++r) {
        float lbr = (float)(r - 1) * CELLW;
        if (lbr * lbr > best + MARGIN) break;
        int zlo = max(cz - r, 0), zhi = min(cz + r, G - 1);
        for (int cz2 = zlo; cz2 <= zhi; ++cz2) {
            int az = abs(cz2 - cz);
            float azd = axis_dist(pz, cz2);
            int ylo = max(cy - r, 0), yhi = min(cy + r, G - 1);
            for (int cy2 = ylo; cy2 <= yhi; ++cy2) {
                int ayz = max(az, abs(cy2 - cy));
                float ay = axis_dist(py, cy2);
                int xlo = max(cx - r, 0), xhi = min(cx + r, G - 1);
                for (int cx2 = xlo; cx2 <= xhi; ++cx2) {
                    if (max(ayz, abs(cx2 - cx)) != r) continue;   // shell only
                    float ax = axis_dist(px, cx2);
                    float lb2 = fmaf(ax, ax, fmaf(ay, ay, azd * azd));
                    if (lb2 > best + MARGIN) continue;
                    scan_cell_s4((cz2 * G + cy2) * G + cx2, q, px, py, pz, psq, best, bidx);
                }
            }
        }
    }
    group_min(best, bidx);   // all 4 lanes now hold the global (d2, idx) min

    // Fused output: id + values row (4 float4s per lane).
    if (q == 0) out[IDS_OFF + orig] = (float)bidx;

    const float4* src = reinterpret_cast<const float4*>(values + (size_t)bidx * D_FEAT);
    float4* dst = reinterpret_cast<float4*>(out + FEATS_OFF + (size_t)orig * D_FEAT);
#pragma unroll
    for (int i = 0; i < 4; ++i)
        dst[q * 4 + i] = src[q * 4 + i];
}

// ---------------------------------------------------------------------------
extern "C" void kernel_launch(void* const* d_in, const int* in_sizes, int n_in,
                              void* d_out, int out_size) {
    const float* pc     = (const float*)d_in[0];
    const float* keys   = (const float*)d_in[1];
    const float* values = (const float*)d_in[2];
    float* out = (float*)d_out;

    zero_kernel<<<(NCELLS + 255) / 256, 256>>>();
    hist_kernel<<<(BN + 255) / 256, 256>>>(pc, keys);
    scan_kernel<<<2, 1024>>>();
    scatter_kernel<<<(BN + 255) / 256, 256>>>(pc, keys);
    argmin_fused_kernel<<<BN * 4 / 256, 256>>>(pc, values, out);
}